// round 15
// baseline (speedup 1.0000x reference)
#include <cuda_runtime.h>
#include <cuda_bf16.h>
#include <cuda_fp16.h>
#include <cstdint>

#define NU 200000
#define NI 200000
#define D  64
#define MAXE 2000000
#define NB_I ((NI + 255) / 256)
#define NB_U ((NU + 255) / 256)

// ---------------------------------------------------------------------------
// Device scratch (no cudaMalloc allowed)
// ---------------------------------------------------------------------------
__device__ float g_acc_i[(size_t)NI * D];
__device__ float g_acc_u[(size_t)NU * D];
__device__ float g_h_i[(size_t)NI * D];
__device__ float g_h_u[(size_t)NU * D];
__device__ __half g_e16_u[(size_t)NU * D];   // fp16 copies for gather
__device__ __half g_e16_i[(size_t)NI * D];
__device__ __half g_h16_i[(size_t)NI * D];
__device__ __half g_h16_u[(size_t)NU * D];
__device__ int g_deg_i[NI];
__device__ int g_deg_u[NU];
__device__ int g_rp_i[NI + 1];
__device__ int g_rp_u[NU + 1];
__device__ int g_cur_i[NI];
__device__ int g_cur_u[NU];
__device__ int g_perm_ui[MAXE];
__device__ int g_perm_iu[MAXE];
__device__ int g_part_i[NB_I];
__device__ int g_part_u[NB_U];
__device__ __nv_bfloat16 g_Bhi[4][64 * 128];
__device__ __nv_bfloat16 g_Blo[4][64 * 128];

__device__ __forceinline__ uint32_t smem_to_u32(const void* p) {
    uint32_t a;
    asm("{ .reg .u64 t; cvta.to.shared.u64 t, %1; cvt.u32.u64 %0, t; }"
        : "=r"(a) : "l"(p));
    return a;
}

// ---------------------------------------------------------------------------
// Prepack weights + zero per-replay state + fp16-convert embeddings.
// ---------------------------------------------------------------------------
__global__ void prep0_k(const float* __restrict__ W1l_ui, const float* __restrict__ W1r_ui,
                        const float* __restrict__ W1l_iu, const float* __restrict__ W1r_iu,
                        const float* __restrict__ W2l_ui, const float* __restrict__ W2r_ui,
                        const float* __restrict__ W2l_iu, const float* __restrict__ W2r_iu,
                        const float* __restrict__ emb_user,
                        const float* __restrict__ emb_item)
{
    int gid = blockIdx.x * blockDim.x + threadIdx.x;
    int stride = gridDim.x * blockDim.x;

    // zero deg + partials
    for (int j = gid; j < NI; j += stride) g_deg_i[j] = 0;
    for (int j = gid; j < NU; j += stride) g_deg_u[j] = 0;
    for (int j = gid; j < NB_I; j += stride) g_part_i[j] = 0;
    for (int j = gid; j < NB_U; j += stride) g_part_u[j] = 0;

    // fp16 conversion of embeddings (float4 -> 2x half2)
    const int QU = NU * D / 4;
    for (int j = gid; j < QU; j += stride) {
        float4 v = reinterpret_cast<const float4*>(emb_user)[j];
        __half2 a = __floats2half2_rn(v.x, v.y);
        __half2 b = __floats2half2_rn(v.z, v.w);
        reinterpret_cast<__half2*>(g_e16_u)[j * 2] = a;
        reinterpret_cast<__half2*>(g_e16_u)[j * 2 + 1] = b;
    }
    const int QI = NI * D / 4;
    for (int j = gid; j < QI; j += stride) {
        float4 v = reinterpret_cast<const float4*>(emb_item)[j];
        __half2 a = __floats2half2_rn(v.x, v.y);
        __half2 b = __floats2half2_rn(v.z, v.w);
        reinterpret_cast<__half2*>(g_e16_i)[j * 2] = a;
        reinterpret_cast<__half2*>(g_e16_i)[j * 2 + 1] = b;
    }

    // weight prepack
    if (gid < 4 * 64 * 128) {
        int set = gid >> 13;
        int n = (gid >> 7) & 63;
        int k = gid & 127;
        const float* Wl; const float* Wr;
        switch (set) {
            case 0: Wl = W1l_ui; Wr = W1r_ui; break;
            case 1: Wl = W1l_iu; Wr = W1r_iu; break;
            case 2: Wl = W2l_ui; Wr = W2r_ui; break;
            default: Wl = W2l_iu; Wr = W2r_iu; break;
        }
        float w = (k < 64) ? Wl[k * D + n] : Wr[(k - 64) * D + n];
        __nv_bfloat16 hi = __float2bfloat16(w);
        __nv_bfloat16 lo = __float2bfloat16(w - __bfloat162float(hi));
        g_Bhi[set][n * 128 + k] = hi;
        g_Blo[set][n * 128 + k] = lo;
    }
}

// ---------------------------------------------------------------------------
// Histogram, both sides
// ---------------------------------------------------------------------------
__global__ void hist2_k(const int* __restrict__ dst0, int E0, int* __restrict__ deg0,
                        const int* __restrict__ dst1, int E1, int* __restrict__ deg1)
{
    int i = blockIdx.x * blockDim.x + threadIdx.x;
    if (i < E0) atomicAdd(&deg0[__ldg(dst0 + i)], 1);
    else if (i < E0 + E1) atomicAdd(&deg1[__ldg(dst1 + (i - E0))], 1);
}

// ---------------------------------------------------------------------------
// Single-kernel exclusive scan via decoupled lookback, both sides.
// ---------------------------------------------------------------------------
__global__ void scan2_k(const int* __restrict__ deg0, int N0,
                        int* __restrict__ rp0, int* __restrict__ cur0, int* part0,
                        const int* __restrict__ deg1, int N1,
                        int* __restrict__ rp1, int* __restrict__ cur1, int* part1,
                        int nb0)
{
    __shared__ int s[256];
    __shared__ int sExcl;
    int tid = threadIdx.x;
    int side = blockIdx.x >= nb0;
    int blk = side ? blockIdx.x - nb0 : blockIdx.x;
    const int* deg = side ? deg1 : deg0;
    int N = side ? N1 : N0;
    int* rowptr = side ? rp1 : rp0;
    int* cursor = side ? cur1 : cur0;
    int* part = side ? part1 : part0;

    int gi = blk * 256 + tid;
    int v = (gi < N) ? deg[gi] : 0;
    s[tid] = v;
    __syncthreads();
    #pragma unroll
    for (int o = 1; o < 256; o <<= 1) {
        int t = (tid >= o) ? s[tid - o] : 0;
        __syncthreads();
        s[tid] += t;
        __syncthreads();
    }

    if (tid == 0) {
        int total = s[255];
        int excl = 0;
        if (blk == 0) {
            __threadfence();
            atomicExch(&part[0], (int)((2u << 30) | (unsigned)total));
        } else {
            __threadfence();
            atomicExch(&part[blk], (int)((1u << 30) | (unsigned)total));
            int i = blk - 1;
            while (1) {
                int p = ((volatile int*)part)[i];
                unsigned up = (unsigned)p;
                unsigned st = up >> 30;
                if (st == 0u) continue;
                excl += (int)(up & 0x3FFFFFFFu);
                if (st >= 2u) break;
                i--;
            }
            __threadfence();
            atomicExch(&part[blk], (int)((2u << 30) | (unsigned)(excl + total)));
        }
        sExcl = excl;
    }
    __syncthreads();

    if (gi < N) {
        int ex = sExcl + s[tid] - v;
        rowptr[gi] = ex;
        cursor[gi] = ex;
        if (gi == N - 1) rowptr[N] = ex + v;
    }
}

__global__ void permute2_k(const int* __restrict__ e0, int E0,
                           int* __restrict__ cur0, int* __restrict__ perm0,
                           const int* __restrict__ e1, int E1,
                           int* __restrict__ cur1, int* __restrict__ perm1)
{
    int i = blockIdx.x * blockDim.x + threadIdx.x;
    if (i < E0) {
        int s = __ldg(e0 + i);
        int d = __ldg(e0 + E0 + i);
        perm0[atomicAdd(&cur0[d], 1)] = s;
    } else if (i < E0 + E1) {
        int j = i - E0;
        int s = __ldg(e1 + j);
        int d = __ldg(e1 + E1 + j);
        perm1[atomicAdd(&cur1[d], 1)] = s;
    }
}

// ---------------------------------------------------------------------------
// Gather-side aggregation (mean), both sides per launch. Warp per row.
// Sources are fp16 (half the gather traffic); accumulation in fp32.
// ---------------------------------------------------------------------------
__global__ void __launch_bounds__(256)
agg2_k(const __half* __restrict__ src0, const int* __restrict__ remap0,
       const int* __restrict__ rp0, const int* __restrict__ perm0,
       float* __restrict__ out0, int N0,
       const __half* __restrict__ src1, const int* __restrict__ remap1,
       const int* __restrict__ rp1, const int* __restrict__ perm1,
       float* __restrict__ out1, int N1)
{
    int w = (blockIdx.x * blockDim.x + threadIdx.x) >> 5;
    int lane = threadIdx.x & 31;
    if (w >= N0 + N1) return;

    const __half* src; const int* remap; const int* rowptr; const int* perm;
    float* outm;
    if (w < N0) {
        src = src0; remap = remap0; rowptr = rp0; perm = perm0; outm = out0;
    } else {
        w -= N0;
        src = src1; remap = remap1; rowptr = rp1; perm = perm1; outm = out1;
    }

    int start = __ldg(rowptr + w);
    int end   = __ldg(rowptr + w + 1);

    float ax = 0.0f, ay = 0.0f;
    for (int base = start; base < end; base += 32) {
        int rem = end - base;
        int idx = 0;
        if (lane < rem) {
            idx = __ldg(perm + base + lane);
            if (remap) idx = __ldg(remap + idx);
        }
        int m = rem < 32 ? rem : 32;
        for (int j = 0; j < m; j++) {
            int s2 = __shfl_sync(0xffffffffu, idx, j);
            __half2 hv = *reinterpret_cast<const __half2*>(
                src + (size_t)s2 * D + lane * 2);
            float2 v = __half22float2(hv);
            ax += v.x;
            ay += v.y;
        }
    }

    int deg = end - start;
    float inv = (deg > 0) ? (1.0f / (float)deg) : 0.0f;
    float2 o;
    o.x = ax * inv;
    o.y = ay * inv;
    *reinterpret_cast<float2*>(outm + (size_t)w * D + lane * 2) = o;
}

// ---------------------------------------------------------------------------
// Post GEMM on tensor cores (R11 inner code), both sides per launch.
// Optionally also writes fp16 copy of the output (for next layer's gather).
// ---------------------------------------------------------------------------
#define PKB 272
#define SM_AHI  0
#define SM_ALO  (128 * PKB)
#define SM_BHI  (2 * 128 * PKB)
#define SM_BLO  (SM_BHI + 64 * PKB)
#define SM_BIAS (SM_BHI + 2 * 64 * PKB)
#define POST_SMEM (SM_BIAS + 256)

#define LDMATRIX_X4(r0, r1, r2, r3, addr) \
    asm volatile("ldmatrix.sync.aligned.m8n8.x4.shared.b16 {%0, %1, %2, %3}, [%4];" \
                 : "=r"(r0), "=r"(r1), "=r"(r2), "=r"(r3) : "r"(addr))

#define MMA_BF16(d, a0, a1, a2, a3, b0, b1) \
    asm volatile("mma.sync.aligned.m16n8k16.row.col.f32.bf16.bf16.f32 " \
                 "{%0, %1, %2, %3}, {%4, %5, %6, %7}, {%8, %9}, {%0, %1, %2, %3};" \
                 : "+f"((d)[0]), "+f"((d)[1]), "+f"((d)[2]), "+f"((d)[3]) \
                 : "r"(a0), "r"(a1), "r"(a2), "r"(a3), "r"(b0), "r"(b1))

__device__ __forceinline__ uint32_t bf2u(__nv_bfloat162 v) {
    return *reinterpret_cast<uint32_t*>(&v);
}

__global__ void __launch_bounds__(256)
sage_post2_tc(const float* __restrict__ acc0, const float* __restrict__ x0,
              const int* __restrict__ remap0,
              const __nv_bfloat16* __restrict__ Bhi0, const __nv_bfloat16* __restrict__ Blo0,
              const float* __restrict__ bl0, float* __restrict__ out0,
              __half* __restrict__ out16_0, int N0, int nb0,
              const float* __restrict__ acc1, const float* __restrict__ x1,
              const int* __restrict__ remap1,
              const __nv_bfloat16* __restrict__ Bhi1, const __nv_bfloat16* __restrict__ Blo1,
              const float* __restrict__ bl1, float* __restrict__ out1,
              __half* __restrict__ out16_1, int N1,
              int relu)
{
    extern __shared__ char smem[];
    uint32_t sb = smem_to_u32(smem);
    const int tid = threadIdx.x;
    const int warp = tid >> 5;
    const int lane = tid & 31;

    const int side = blockIdx.x >= nb0;
    const float* acc = side ? acc1 : acc0;
    const float* xdst_base = side ? x1 : x0;
    const int* remap = side ? remap1 : remap0;
    const __nv_bfloat16* Bhi = side ? Bhi1 : Bhi0;
    const __nv_bfloat16* Blo = side ? Blo1 : Blo0;
    const float* bl = side ? bl1 : bl0;
    float* out = side ? out1 : out0;
    __half* out16 = side ? out16_1 : out16_0;
    const int N = side ? N1 : N0;
    const int r0 = (side ? blockIdx.x - nb0 : blockIdx.x) * 128;

    // ---- Stage B from prepacked global ----
    #pragma unroll
    for (int pp = 0; pp < 4; pp++) {
        int i = tid + pp * 256;
        int n = i >> 4;
        int kq = i & 15;
        *reinterpret_cast<uint4*>(smem + SM_BHI + n * PKB + kq * 16) =
            *reinterpret_cast<const uint4*>(Bhi + n * 128 + kq * 8);
        *reinterpret_cast<uint4*>(smem + SM_BLO + n * PKB + kq * 16) =
            *reinterpret_cast<const uint4*>(Blo + n * 128 + kq * 8);
    }
    if (tid < 64) *reinterpret_cast<float*>(smem + SM_BIAS + tid * 4) = bl[tid];

    // ---- Stage A ----
    {
        int row  = tid & 127;
        int half = tid >> 7;
        int gr   = r0 + row;
        bool ok  = (gr < N);
        const float* p;
        if (half == 0) {
            p = acc + (size_t)(ok ? gr : 0) * D;
        } else {
            int xr = ok ? (remap ? __ldg(remap + gr) : gr) : 0;
            p = xdst_base + (size_t)xr * D;
        }
        char* aHiRow = smem + SM_AHI + row * PKB + half * 128;
        char* aLoRow = smem + SM_ALO + row * PKB + half * 128;
        #pragma unroll
        for (int j = 0; j < 8; j++) {
            float4 v0 = ok ? reinterpret_cast<const float4*>(p)[j * 2]
                           : make_float4(0.f, 0.f, 0.f, 0.f);
            float4 v1 = ok ? reinterpret_cast<const float4*>(p)[j * 2 + 1]
                           : make_float4(0.f, 0.f, 0.f, 0.f);
            __nv_bfloat162 h0 = __float22bfloat162_rn(make_float2(v0.x, v0.y));
            __nv_bfloat162 h1 = __float22bfloat162_rn(make_float2(v0.z, v0.w));
            __nv_bfloat162 h2 = __float22bfloat162_rn(make_float2(v1.x, v1.y));
            __nv_bfloat162 h3 = __float22bfloat162_rn(make_float2(v1.z, v1.w));
            float2 f0 = __bfloat1622float2(h0);
            float2 f1 = __bfloat1622float2(h1);
            float2 f2 = __bfloat1622float2(h2);
            float2 f3 = __bfloat1622float2(h3);
            __nv_bfloat162 l0 = __float22bfloat162_rn(make_float2(v0.x - f0.x, v0.y - f0.y));
            __nv_bfloat162 l1 = __float22bfloat162_rn(make_float2(v0.z - f1.x, v0.w - f1.y));
            __nv_bfloat162 l2 = __float22bfloat162_rn(make_float2(v1.x - f2.x, v1.y - f2.y));
            __nv_bfloat162 l3 = __float22bfloat162_rn(make_float2(v1.z - f3.x, v1.w - f3.y));
            *reinterpret_cast<uint4*>(aHiRow + j * 16) =
                make_uint4(bf2u(h0), bf2u(h1), bf2u(h2), bf2u(h3));
            *reinterpret_cast<uint4*>(aLoRow + j * 16) =
                make_uint4(bf2u(l0), bf2u(l1), bf2u(l2), bf2u(l3));
        }
    }
    __syncthreads();

    // ---- MMA mainloop: 3 passes x 8 k-steps, 8 n-tiles ----
    float d[8][4];
    #pragma unroll
    for (int t = 0; t < 8; t++) {
        d[t][0] = 0.f; d[t][1] = 0.f; d[t][2] = 0.f; d[t][3] = 0.f;
    }

    const uint32_t aRowOff = (uint32_t)(warp * 16 + (lane & 15)) * PKB
                           + (uint32_t)(lane >> 4) * 16;
    const uint32_t bRowOff = (uint32_t)(lane >> 2) * PKB + (uint32_t)(lane & 3) * 4;

    #pragma unroll
    for (int pass = 0; pass < 3; pass++) {
        uint32_t aBase = sb + (pass == 1 ? SM_ALO : SM_AHI) + aRowOff;
        uint32_t bOff  = (pass == 2 ? SM_BLO : SM_BHI) + bRowOff;
        #pragma unroll
        for (int ks = 0; ks < 8; ks++) {
            uint32_t a0, a1, a2, a3;
            LDMATRIX_X4(a0, a1, a2, a3, aBase + ks * 32);
            #pragma unroll
            for (int t = 0; t < 8; t++) {
                uint32_t b0 = *reinterpret_cast<const uint32_t*>(
                    (const char*)smem + bOff + t * 8 * PKB + ks * 32);
                uint32_t b1 = *reinterpret_cast<const uint32_t*>(
                    (const char*)smem + bOff + t * 8 * PKB + ks * 32 + 16);
                MMA_BF16(d[t], a0, a1, a2, a3, b0, b1);
            }
        }
    }

    // ---- Epilogue ----
    const float* bias = reinterpret_cast<const float*>(smem + SM_BIAS);
    int cBase = (lane & 3) * 2;
    float ssl = 0.f, ssh = 0.f;
    #pragma unroll
    for (int t = 0; t < 8; t++) {
        int c = t * 8 + cBase;
        float b0 = bias[c], b1 = bias[c + 1];
        d[t][0] += b0; d[t][1] += b1;
        d[t][2] += b0; d[t][3] += b1;
        ssl = fmaf(d[t][0], d[t][0], ssl); ssl = fmaf(d[t][1], d[t][1], ssl);
        ssh = fmaf(d[t][2], d[t][2], ssh); ssh = fmaf(d[t][3], d[t][3], ssh);
    }
    ssl += __shfl_xor_sync(0xffffffffu, ssl, 1);
    ssl += __shfl_xor_sync(0xffffffffu, ssl, 2);
    ssh += __shfl_xor_sync(0xffffffffu, ssh, 1);
    ssh += __shfl_xor_sync(0xffffffffu, ssh, 2);

    int rlo = r0 + warp * 16 + (lane >> 2);
    int rhi = rlo + 8;
    float invl = 1.0f / fmaxf(sqrtf(ssl), 1e-12f);
    float invh = 1.0f / fmaxf(sqrtf(ssh), 1e-12f);

    if (rlo < N) {
        float* op = out + (size_t)rlo * D + cBase;
        #pragma unroll
        for (int t = 0; t < 8; t++) {
            float2 v = make_float2(d[t][0] * invl, d[t][1] * invl);
            if (relu) { v.x = fmaxf(v.x, 0.f); v.y = fmaxf(v.y, 0.f); }
            *reinterpret_cast<float2*>(op + t * 8) = v;
            if (out16) {
                *reinterpret_cast<__half2*>(out16 + (size_t)rlo * D + cBase + t * 8) =
                    __floats2half2_rn(v.x, v.y);
            }
        }
    }
    if (rhi < N) {
        float* op = out + (size_t)rhi * D + cBase;
        #pragma unroll
        for (int t = 0; t < 8; t++) {
            float2 v = make_float2(d[t][2] * invh, d[t][3] * invh);
            if (relu) { v.x = fmaxf(v.x, 0.f); v.y = fmaxf(v.y, 0.f); }
            *reinterpret_cast<float2*>(op + t * 8) = v;
            if (out16) {
                *reinterpret_cast<__half2*>(out16 + (size_t)rhi * D + cBase + t * 8) =
                    __floats2half2_rn(v.x, v.y);
            }
        }
    }
}

// ---------------------------------------------------------------------------
// Launch
// ---------------------------------------------------------------------------
extern "C" void kernel_launch(void* const* d_in, const int* in_sizes, int n_in,
                              void* d_out, int out_size)
{
    const float* emb_user = (const float*)d_in[0];
    const float* emb_item = (const float*)d_in[1];
    const float* W1l_ui = (const float*)d_in[2];
    const float* b1_ui  = (const float*)d_in[3];
    const float* W1r_ui = (const float*)d_in[4];
    const float* W1l_iu = (const float*)d_in[5];
    const float* b1_iu  = (const float*)d_in[6];
    const float* W1r_iu = (const float*)d_in[7];
    const float* W2l_ui = (const float*)d_in[8];
    const float* b2_ui  = (const float*)d_in[9];
    const float* W2r_ui = (const float*)d_in[10];
    const float* W2l_iu = (const float*)d_in[11];
    const float* b2_iu  = (const float*)d_in[12];
    const float* W2r_iu = (const float*)d_in[13];
    const int* n_id_user = (const int*)d_in[14];
    const int* n_id_item = (const int*)d_in[15];
    const int* edge_ui   = (const int*)d_in[16];
    const int* edge_iu   = (const int*)d_in[17];

    const int E_ui = in_sizes[16] / 2;
    const int E_iu = in_sizes[17] / 2;

    float* out = (float*)d_out;
    float* out_user = out;
    float* out_item = out + (size_t)NU * D;

    float *acc_i, *acc_u, *h_i, *h_u;
    __half *e16_u, *e16_i, *h16_i, *h16_u;
    int *deg_i, *deg_u, *rp_i, *rp_u, *cur_i, *cur_u, *perm_ui, *perm_iu;
    int *part_i, *part_u;
    __nv_bfloat16 *Bhi, *Blo;
    cudaGetSymbolAddress((void**)&acc_i, g_acc_i);
    cudaGetSymbolAddress((void**)&acc_u, g_acc_u);
    cudaGetSymbolAddress((void**)&h_i, g_h_i);
    cudaGetSymbolAddress((void**)&h_u, g_h_u);
    cudaGetSymbolAddress((void**)&e16_u, g_e16_u);
    cudaGetSymbolAddress((void**)&e16_i, g_e16_i);
    cudaGetSymbolAddress((void**)&h16_i, g_h16_i);
    cudaGetSymbolAddress((void**)&h16_u, g_h16_u);
    cudaGetSymbolAddress((void**)&deg_i, g_deg_i);
    cudaGetSymbolAddress((void**)&deg_u, g_deg_u);
    cudaGetSymbolAddress((void**)&rp_i, g_rp_i);
    cudaGetSymbolAddress((void**)&rp_u, g_rp_u);
    cudaGetSymbolAddress((void**)&cur_i, g_cur_i);
    cudaGetSymbolAddress((void**)&cur_u, g_cur_u);
    cudaGetSymbolAddress((void**)&perm_ui, g_perm_ui);
    cudaGetSymbolAddress((void**)&perm_iu, g_perm_iu);
    cudaGetSymbolAddress((void**)&part_i, g_part_i);
    cudaGetSymbolAddress((void**)&part_u, g_part_u);
    cudaGetSymbolAddress((void**)&Bhi, g_Bhi);
    cudaGetSymbolAddress((void**)&Blo, g_Blo);

    const int TPB = 256;
    const int eBlocks2 = (E_ui + E_iu + TPB - 1) / TPB;
    const int aggBlocks2 = (int)(((long long)(NI + NU) * 32 + TPB - 1) / TPB);
    const int postBlocksI = (NI + 127) / 128;
    const int postBlocksU = (NU + 127) / 128;

    cudaFuncSetAttribute(sage_post2_tc,
                         cudaFuncAttributeMaxDynamicSharedMemorySize, POST_SMEM);

    // 0: prepack weights + zero state + fp16 embedding copies
    prep0_k<<<800, 256>>>(W1l_ui, W1r_ui, W1l_iu, W1r_iu,
                          W2l_ui, W2r_ui, W2l_iu, W2r_iu,
                          emb_user, emb_item);
    // 1: histogram
    hist2_k<<<eBlocks2, TPB>>>(edge_ui + E_ui, E_ui, deg_i,
                               edge_iu + E_iu, E_iu, deg_u);
    // 2: lookback scan
    scan2_k<<<NB_I + NB_U, 256>>>(deg_i, NI, rp_i, cur_i, part_i,
                                  deg_u, NU, rp_u, cur_u, part_u, NB_I);
    // 3: permute
    permute2_k<<<eBlocks2, TPB>>>(edge_ui, E_ui, cur_i, perm_ui,
                                  edge_iu, E_iu, cur_u, perm_iu);

    // 4: layer-1 aggregation (fp16 gather sources)
    agg2_k<<<aggBlocks2, TPB>>>(e16_u, n_id_user, rp_i, perm_ui, acc_i, NI,
                                e16_i, n_id_item, rp_u, perm_iu, acc_u, NU);
    // 5: layer-1 post (writes fp32 h + fp16 h copies)
    sage_post2_tc<<<postBlocksI + postBlocksU, TPB, POST_SMEM>>>(
        acc_i, emb_item, n_id_item, Bhi + 0 * 8192, Blo + 0 * 8192, b1_ui,
        h_i, h16_i, NI, postBlocksI,
        acc_u, emb_user, n_id_user, Bhi + 1 * 8192, Blo + 1 * 8192, b1_iu,
        h_u, h16_u, NU,
        1);

    // 6: layer-2 aggregation (fp16 gather of h)
    agg2_k<<<aggBlocks2, TPB>>>(h16_u, nullptr, rp_i, perm_ui, acc_i, NI,
                                h16_i, nullptr, rp_u, perm_iu, acc_u, NU);
    // 7: layer-2 post (final outputs, no fp16 copies)
    sage_post2_tc<<<postBlocksI + postBlocksU, TPB, POST_SMEM>>>(
        acc_i, h_i, nullptr, Bhi + 2 * 8192, Blo + 2 * 8192, b2_ui,
        out_item, nullptr, NI, postBlocksI,
        acc_u, h_u, nullptr, Bhi + 3 * 8192, Blo + 3 * 8192, b2_iu,
        out_user, nullptr, NU,
        0);
}

// round 16
// speedup vs baseline: 1.1189x; 1.1189x over previous
#include <cuda_runtime.h>
#include <cuda_bf16.h>
#include <cuda_fp16.h>
#include <cstdint>

#define NU 200000
#define NI 200000
#define D  64
#define MAXE 2000000
#define NB_I ((NI + 255) / 256)
#define NB_U ((NU + 255) / 256)

// ---------------------------------------------------------------------------
// Device scratch (no cudaMalloc allowed)
// ---------------------------------------------------------------------------
__device__ float g_acc_i[(size_t)NI * D];
__device__ float g_acc_u[(size_t)NU * D];
__device__ float g_h_i[(size_t)NI * D];
__device__ float g_h_u[(size_t)NU * D];
__device__ int g_deg_i[NI];
__device__ int g_deg_u[NU];
__device__ int g_rp_i[NI + 1];
__device__ int g_rp_u[NU + 1];
__device__ int g_cur_i[NI];
__device__ int g_cur_u[NU];
__device__ int g_perm_ui[MAXE];
__device__ int g_perm_iu[MAXE];
__device__ int g_bsum_i[1024];
__device__ int g_boff_i[1024];
__device__ int g_bsum_u[1024];
__device__ int g_boff_u[1024];
__device__ __half g_B16[4][64 * 128];   // prepacked W^T, fp16

__device__ __forceinline__ uint32_t smem_to_u32(const void* p) {
    uint32_t a;
    asm("{ .reg .u64 t; cvta.to.shared.u64 t, %1; cvt.u32.u64 %0, t; }"
        : "=r"(a) : "l"(p));
    return a;
}

// ---------------------------------------------------------------------------
// Weight prepack: B[set][n][k] = (k<64 ? Wl[k][n] : Wr[k-64][n]) as fp16
// ---------------------------------------------------------------------------
__global__ void prepack_w_k(const float* __restrict__ W1l_ui, const float* __restrict__ W1r_ui,
                            const float* __restrict__ W1l_iu, const float* __restrict__ W1r_iu,
                            const float* __restrict__ W2l_ui, const float* __restrict__ W2r_ui,
                            const float* __restrict__ W2l_iu, const float* __restrict__ W2r_iu)
{
    int i = blockIdx.x * blockDim.x + threadIdx.x;
    if (i >= 4 * 64 * 128) return;
    int set = i >> 13;
    int n = (i >> 7) & 63;
    int k = i & 127;
    const float* Wl; const float* Wr;
    switch (set) {
        case 0: Wl = W1l_ui; Wr = W1r_ui; break;
        case 1: Wl = W1l_iu; Wr = W1r_iu; break;
        case 2: Wl = W2l_ui; Wr = W2r_ui; break;
        default: Wl = W2l_iu; Wr = W2r_iu; break;
    }
    float w = (k < 64) ? Wl[k * D + n] : Wr[(k - 64) * D + n];
    g_B16[set][n * 128 + k] = __float2half_rn(w);
}

// ---------------------------------------------------------------------------
// CSR build — both sides per launch (R11 versions)
// ---------------------------------------------------------------------------
__global__ void hist2_k(const int* __restrict__ dst0, int E0, int* __restrict__ deg0,
                        const int* __restrict__ dst1, int E1, int* __restrict__ deg1)
{
    int i = blockIdx.x * blockDim.x + threadIdx.x;
    if (i < E0) atomicAdd(&deg0[__ldg(dst0 + i)], 1);
    else if (i < E0 + E1) atomicAdd(&deg1[__ldg(dst1 + (i - E0))], 1);
}

__global__ void scanA2_k(const int* __restrict__ deg0, int N0, int* __restrict__ bsum0,
                         const int* __restrict__ deg1, int N1, int* __restrict__ bsum1,
                         int nb0)
{
    __shared__ int s[256];
    int tid = threadIdx.x;
    int side = blockIdx.x >= nb0;
    int blk = side ? blockIdx.x - nb0 : blockIdx.x;
    const int* deg = side ? deg1 : deg0;
    int N = side ? N1 : N0;
    int* bsum = side ? bsum1 : bsum0;
    int i = blk * 256 + tid;
    s[tid] = (i < N) ? deg[i] : 0;
    __syncthreads();
    #pragma unroll
    for (int o = 128; o; o >>= 1) {
        if (tid < o) s[tid] += s[tid + o];
        __syncthreads();
    }
    if (tid == 0) bsum[blk] = s[0];
}

__global__ void scanB2_k(const int* __restrict__ bsum0, int NB0, int* __restrict__ boff0,
                         int* __restrict__ rp0, int N0,
                         const int* __restrict__ bsum1, int NB1, int* __restrict__ boff1,
                         int* __restrict__ rp1, int N1)
{
    __shared__ int s[1024];
    int tid = threadIdx.x;
    const int* bsum = blockIdx.x ? bsum1 : bsum0;
    int NB = blockIdx.x ? NB1 : NB0;
    int* boff = blockIdx.x ? boff1 : boff0;
    int* rowptr = blockIdx.x ? rp1 : rp0;
    int N = blockIdx.x ? N1 : N0;
    int v = (tid < NB) ? bsum[tid] : 0;
    s[tid] = v;
    __syncthreads();
    for (int o = 1; o < 1024; o <<= 1) {
        int t = (tid >= o) ? s[tid - o] : 0;
        __syncthreads();
        s[tid] += t;
        __syncthreads();
    }
    if (tid < NB) boff[tid] = s[tid] - v;
    if (tid == NB - 1) rowptr[N] = s[tid];
}

__global__ void scanC2_k(const int* __restrict__ deg0, int N0, const int* __restrict__ boff0,
                         int* __restrict__ rp0, int* __restrict__ cur0,
                         const int* __restrict__ deg1, int N1, const int* __restrict__ boff1,
                         int* __restrict__ rp1, int* __restrict__ cur1,
                         int nb0)
{
    __shared__ int s[256];
    int tid = threadIdx.x;
    int side = blockIdx.x >= nb0;
    int blk = side ? blockIdx.x - nb0 : blockIdx.x;
    const int* deg = side ? deg1 : deg0;
    const int* boff = side ? boff1 : boff0;
    int N = side ? N1 : N0;
    int* rowptr = side ? rp1 : rp0;
    int* cursor = side ? cur1 : cur0;
    int i = blk * 256 + tid;
    int v = (i < N) ? deg[i] : 0;
    s[tid] = v;
    __syncthreads();
    #pragma unroll
    for (int o = 1; o < 256; o <<= 1) {
        int t = (tid >= o) ? s[tid - o] : 0;
        __syncthreads();
        s[tid] += t;
        __syncthreads();
    }
    if (i < N) {
        int ex = boff[blk] + s[tid] - v;
        rowptr[i] = ex;
        cursor[i] = ex;
    }
}

__global__ void permute2_k(const int* __restrict__ e0, int E0,
                           int* __restrict__ cur0, int* __restrict__ perm0,
                           const int* __restrict__ e1, int E1,
                           int* __restrict__ cur1, int* __restrict__ perm1)
{
    int i = blockIdx.x * blockDim.x + threadIdx.x;
    if (i < E0) {
        int s = __ldg(e0 + i);
        int d = __ldg(e0 + E0 + i);
        perm0[atomicAdd(&cur0[d], 1)] = s;
    } else if (i < E0 + E1) {
        int j = i - E0;
        int s = __ldg(e1 + j);
        int d = __ldg(e1 + E1 + j);
        perm1[atomicAdd(&cur1[d], 1)] = s;
    }
}

// ---------------------------------------------------------------------------
// Gather-side aggregation (mean), fp32 sources (R11 verbatim).
// ---------------------------------------------------------------------------
__global__ void __launch_bounds__(256)
agg2_k(const float* __restrict__ src0, const int* __restrict__ remap0,
       const int* __restrict__ rp0, const int* __restrict__ perm0,
       float* __restrict__ out0, int N0,
       const float* __restrict__ src1, const int* __restrict__ remap1,
       const int* __restrict__ rp1, const int* __restrict__ perm1,
       float* __restrict__ out1, int N1)
{
    int w = (blockIdx.x * blockDim.x + threadIdx.x) >> 5;
    int lane = threadIdx.x & 31;
    if (w >= N0 + N1) return;

    const float* src; const int* remap; const int* rowptr; const int* perm;
    float* outm;
    if (w < N0) {
        src = src0; remap = remap0; rowptr = rp0; perm = perm0; outm = out0;
    } else {
        w -= N0;
        src = src1; remap = remap1; rowptr = rp1; perm = perm1; outm = out1;
    }

    int start = __ldg(rowptr + w);
    int end   = __ldg(rowptr + w + 1);

    float ax = 0.0f, ay = 0.0f;
    for (int base = start; base < end; base += 32) {
        int rem = end - base;
        int idx = 0;
        if (lane < rem) {
            idx = __ldg(perm + base + lane);
            if (remap) idx = __ldg(remap + idx);
        }
        int m = rem < 32 ? rem : 32;
        for (int j = 0; j < m; j++) {
            int s2 = __shfl_sync(0xffffffffu, idx, j);
            float2 v = *reinterpret_cast<const float2*>(src + (size_t)s2 * D + lane * 2);
            ax += v.x;
            ay += v.y;
        }
    }

    int deg = end - start;
    float inv = (deg > 0) ? (1.0f / (float)deg) : 0.0f;
    float2 o;
    o.x = ax * inv;
    o.y = ay * inv;
    *reinterpret_cast<float2*>(outm + (size_t)w * D + lane * 2) = o;
}

// ---------------------------------------------------------------------------
// Post GEMM on tensor cores — SINGLE-PASS fp16 MMA (m16n8k16.f32.f16.f16.f32).
// 128-row tile, single A plane + single B plane: 53KB smem -> 4 blocks/SM.
// Same warp layout / epilogue as the proven R11 kernel.
// ---------------------------------------------------------------------------
#define PKB 272
#define SM_A    0
#define SM_B    (128 * PKB)            // 34816
#define SM_BIAS (SM_B + 64 * PKB)      // 52224
#define POST_SMEM (SM_BIAS + 256)

#define LDMATRIX_X4(r0, r1, r2, r3, addr) \
    asm volatile("ldmatrix.sync.aligned.m8n8.x4.shared.b16 {%0, %1, %2, %3}, [%4];" \
                 : "=r"(r0), "=r"(r1), "=r"(r2), "=r"(r3) : "r"(addr))

#define MMA_F16(d, a0, a1, a2, a3, b0, b1) \
    asm volatile("mma.sync.aligned.m16n8k16.row.col.f32.f16.f16.f32 " \
                 "{%0, %1, %2, %3}, {%4, %5, %6, %7}, {%8, %9}, {%0, %1, %2, %3};" \
                 : "+f"((d)[0]), "+f"((d)[1]), "+f"((d)[2]), "+f"((d)[3]) \
                 : "r"(a0), "r"(a1), "r"(a2), "r"(a3), "r"(b0), "r"(b1))

__device__ __forceinline__ uint32_t h2u(__half2 v) {
    return *reinterpret_cast<uint32_t*>(&v);
}

__global__ void __launch_bounds__(256)
sage_post2_tc(const float* __restrict__ acc0, const float* __restrict__ x0,
              const int* __restrict__ remap0,
              const __half* __restrict__ B0,
              const float* __restrict__ bl0, float* __restrict__ out0, int N0, int nb0,
              const float* __restrict__ acc1, const float* __restrict__ x1,
              const int* __restrict__ remap1,
              const __half* __restrict__ B1,
              const float* __restrict__ bl1, float* __restrict__ out1, int N1,
              int relu)
{
    extern __shared__ char smem[];
    uint32_t sb = smem_to_u32(smem);
    const int tid = threadIdx.x;
    const int warp = tid >> 5;
    const int lane = tid & 31;

    const int side = blockIdx.x >= nb0;
    const float* acc = side ? acc1 : acc0;
    const float* xdst_base = side ? x1 : x0;
    const int* remap = side ? remap1 : remap0;
    const __half* B = side ? B1 : B0;
    const float* bl = side ? bl1 : bl0;
    float* out = side ? out1 : out0;
    const int N = side ? N1 : N0;
    const int r0 = (side ? blockIdx.x - nb0 : blockIdx.x) * 128;

    // ---- Stage B (fp16, vectorized) ----
    #pragma unroll
    for (int pp = 0; pp < 4; pp++) {
        int i = tid + pp * 256;        // f4 idx 0..1023 over [64 n][16 chunks]
        int n = i >> 4;
        int kq = i & 15;
        *reinterpret_cast<uint4*>(smem + SM_B + n * PKB + kq * 16) =
            *reinterpret_cast<const uint4*>(B + n * 128 + kq * 8);
    }
    if (tid < 64) *reinterpret_cast<float*>(smem + SM_BIAS + tid * 4) = bl[tid];

    // ---- Stage A (fp16 single plane): row = tid&127, half = tid>>7 ----
    {
        int row  = tid & 127;
        int half = tid >> 7;
        int gr   = r0 + row;
        bool ok  = (gr < N);
        const float* p;
        if (half == 0) {
            p = acc + (size_t)(ok ? gr : 0) * D;
        } else {
            int xr = ok ? (remap ? __ldg(remap + gr) : gr) : 0;
            p = xdst_base + (size_t)xr * D;
        }
        char* aRow = smem + SM_A + row * PKB + half * 128;
        #pragma unroll
        for (int j = 0; j < 8; j++) {
            float4 v0 = ok ? reinterpret_cast<const float4*>(p)[j * 2]
                           : make_float4(0.f, 0.f, 0.f, 0.f);
            float4 v1 = ok ? reinterpret_cast<const float4*>(p)[j * 2 + 1]
                           : make_float4(0.f, 0.f, 0.f, 0.f);
            __half2 h0 = __floats2half2_rn(v0.x, v0.y);
            __half2 h1 = __floats2half2_rn(v0.z, v0.w);
            __half2 h2 = __floats2half2_rn(v1.x, v1.y);
            __half2 h3 = __floats2half2_rn(v1.z, v1.w);
            *reinterpret_cast<uint4*>(aRow + j * 16) =
                make_uint4(h2u(h0), h2u(h1), h2u(h2), h2u(h3));
        }
    }
    __syncthreads();

    // ---- MMA mainloop: SINGLE pass, 8 k-steps, 8 n-tiles ----
    float d[8][4];
    #pragma unroll
    for (int t = 0; t < 8; t++) {
        d[t][0] = 0.f; d[t][1] = 0.f; d[t][2] = 0.f; d[t][3] = 0.f;
    }

    const uint32_t aRowOff = (uint32_t)(warp * 16 + (lane & 15)) * PKB
                           + (uint32_t)(lane >> 4) * 16;
    const uint32_t bRowOff = (uint32_t)(lane >> 2) * PKB + (uint32_t)(lane & 3) * 4;

    const uint32_t aBase = sb + SM_A + aRowOff;
    #pragma unroll
    for (int ks = 0; ks < 8; ks++) {
        uint32_t a0, a1, a2, a3;
        LDMATRIX_X4(a0, a1, a2, a3, aBase + ks * 32);
        #pragma unroll
        for (int t = 0; t < 8; t++) {
            uint32_t b0 = *reinterpret_cast<const uint32_t*>(
                (const char*)smem + SM_B + bRowOff + t * 8 * PKB + ks * 32);
            uint32_t b1 = *reinterpret_cast<const uint32_t*>(
                (const char*)smem + SM_B + bRowOff + t * 8 * PKB + ks * 32 + 16);
            MMA_F16(d[t], a0, a1, a2, a3, b0, b1);
        }
    }

    // ---- Epilogue (R11 verbatim) ----
    const float* bias = reinterpret_cast<const float*>(smem + SM_BIAS);
    int cBase = (lane & 3) * 2;
    float ssl = 0.f, ssh = 0.f;
    #pragma unroll
    for (int t = 0; t < 8; t++) {
        int c = t * 8 + cBase;
        float b0 = bias[c], b1 = bias[c + 1];
        d[t][0] += b0; d[t][1] += b1;
        d[t][2] += b0; d[t][3] += b1;
        ssl = fmaf(d[t][0], d[t][0], ssl); ssl = fmaf(d[t][1], d[t][1], ssl);
        ssh = fmaf(d[t][2], d[t][2], ssh); ssh = fmaf(d[t][3], d[t][3], ssh);
    }
    ssl += __shfl_xor_sync(0xffffffffu, ssl, 1);
    ssl += __shfl_xor_sync(0xffffffffu, ssl, 2);
    ssh += __shfl_xor_sync(0xffffffffu, ssh, 1);
    ssh += __shfl_xor_sync(0xffffffffu, ssh, 2);

    int rlo = r0 + warp * 16 + (lane >> 2);
    int rhi = rlo + 8;
    float invl = 1.0f / fmaxf(sqrtf(ssl), 1e-12f);
    float invh = 1.0f / fmaxf(sqrtf(ssh), 1e-12f);

    if (rlo < N) {
        float* op = out + (size_t)rlo * D + cBase;
        #pragma unroll
        for (int t = 0; t < 8; t++) {
            float2 v = make_float2(d[t][0] * invl, d[t][1] * invl);
            if (relu) { v.x = fmaxf(v.x, 0.f); v.y = fmaxf(v.y, 0.f); }
            *reinterpret_cast<float2*>(op + t * 8) = v;
        }
    }
    if (rhi < N) {
        float* op = out + (size_t)rhi * D + cBase;
        #pragma unroll
        for (int t = 0; t < 8; t++) {
            float2 v = make_float2(d[t][2] * invh, d[t][3] * invh);
            if (relu) { v.x = fmaxf(v.x, 0.f); v.y = fmaxf(v.y, 0.f); }
            *reinterpret_cast<float2*>(op + t * 8) = v;
        }
    }
}

// ---------------------------------------------------------------------------
// Launch (R11 structure)
// ---------------------------------------------------------------------------
extern "C" void kernel_launch(void* const* d_in, const int* in_sizes, int n_in,
                              void* d_out, int out_size)
{
    const float* emb_user = (const float*)d_in[0];
    const float* emb_item = (const float*)d_in[1];
    const float* W1l_ui = (const float*)d_in[2];
    const float* b1_ui  = (const float*)d_in[3];
    const float* W1r_ui = (const float*)d_in[4];
    const float* W1l_iu = (const float*)d_in[5];
    const float* b1_iu  = (const float*)d_in[6];
    const float* W1r_iu = (const float*)d_in[7];
    const float* W2l_ui = (const float*)d_in[8];
    const float* b2_ui  = (const float*)d_in[9];
    const float* W2r_ui = (const float*)d_in[10];
    const float* W2l_iu = (const float*)d_in[11];
    const float* b2_iu  = (const float*)d_in[12];
    const float* W2r_iu = (const float*)d_in[13];
    const int* n_id_user = (const int*)d_in[14];
    const int* n_id_item = (const int*)d_in[15];
    const int* edge_ui   = (const int*)d_in[16];
    const int* edge_iu   = (const int*)d_in[17];

    const int E_ui = in_sizes[16] / 2;
    const int E_iu = in_sizes[17] / 2;

    float* out = (float*)d_out;
    float* out_user = out;
    float* out_item = out + (size_t)NU * D;

    float *acc_i, *acc_u, *h_i, *h_u;
    int *deg_i, *deg_u, *rp_i, *rp_u, *cur_i, *cur_u, *perm_ui, *perm_iu;
    int *bsum_i, *boff_i, *bsum_u, *boff_u;
    __half* B16;
    cudaGetSymbolAddress((void**)&acc_i, g_acc_i);
    cudaGetSymbolAddress((void**)&acc_u, g_acc_u);
    cudaGetSymbolAddress((void**)&h_i, g_h_i);
    cudaGetSymbolAddress((void**)&h_u, g_h_u);
    cudaGetSymbolAddress((void**)&deg_i, g_deg_i);
    cudaGetSymbolAddress((void**)&deg_u, g_deg_u);
    cudaGetSymbolAddress((void**)&rp_i, g_rp_i);
    cudaGetSymbolAddress((void**)&rp_u, g_rp_u);
    cudaGetSymbolAddress((void**)&cur_i, g_cur_i);
    cudaGetSymbolAddress((void**)&cur_u, g_cur_u);
    cudaGetSymbolAddress((void**)&perm_ui, g_perm_ui);
    cudaGetSymbolAddress((void**)&perm_iu, g_perm_iu);
    cudaGetSymbolAddress((void**)&bsum_i, g_bsum_i);
    cudaGetSymbolAddress((void**)&boff_i, g_boff_i);
    cudaGetSymbolAddress((void**)&bsum_u, g_bsum_u);
    cudaGetSymbolAddress((void**)&boff_u, g_boff_u);
    cudaGetSymbolAddress((void**)&B16, g_B16);

    const int TPB = 256;
    const int eBlocks2 = (E_ui + E_iu + TPB - 1) / TPB;
    const int aggBlocks2 = (int)(((long long)(NI + NU) * 32 + TPB - 1) / TPB);
    const int postBlocksI = (NI + 127) / 128;
    const int postBlocksU = (NU + 127) / 128;

    cudaFuncSetAttribute(sage_post2_tc,
                         cudaFuncAttributeMaxDynamicSharedMemorySize, POST_SMEM);

    // ---- Prepack + CSR build (merged) ----
    prepack_w_k<<<128, 256>>>(W1l_ui, W1r_ui, W1l_iu, W1r_iu,
                              W2l_ui, W2r_ui, W2l_iu, W2r_iu);

    cudaMemsetAsync(deg_i, 0, NI * sizeof(int));
    cudaMemsetAsync(deg_u, 0, NU * sizeof(int));

    hist2_k<<<eBlocks2, TPB>>>(edge_ui + E_ui, E_ui, deg_i,
                               edge_iu + E_iu, E_iu, deg_u);
    scanA2_k<<<NB_I + NB_U, 256>>>(deg_i, NI, bsum_i, deg_u, NU, bsum_u, NB_I);
    scanB2_k<<<2, 1024>>>(bsum_i, NB_I, boff_i, rp_i, NI,
                          bsum_u, NB_U, boff_u, rp_u, NU);
    scanC2_k<<<NB_I + NB_U, 256>>>(deg_i, NI, boff_i, rp_i, cur_i,
                                   deg_u, NU, boff_u, rp_u, cur_u, NB_I);
    permute2_k<<<eBlocks2, TPB>>>(edge_ui, E_ui, cur_i, perm_ui,
                                  edge_iu, E_iu, cur_u, perm_iu);

    // ---- Layer 1 ----
    agg2_k<<<aggBlocks2, TPB>>>(emb_user, n_id_user, rp_i, perm_ui, acc_i, NI,
                                emb_item, n_id_item, rp_u, perm_iu, acc_u, NU);
    sage_post2_tc<<<postBlocksI + postBlocksU, TPB, POST_SMEM>>>(
        acc_i, emb_item, n_id_item, B16 + 0 * 8192, b1_ui, h_i, NI, postBlocksI,
        acc_u, emb_user, n_id_user, B16 + 1 * 8192, b1_iu, h_u, NU,
        1);

    // ---- Layer 2 ----
    agg2_k<<<aggBlocks2, TPB>>>(h_u, nullptr, rp_i, perm_ui, acc_i, NI,
                                h_i, nullptr, rp_u, perm_iu, acc_u, NU);
    sage_post2_tc<<<postBlocksI + postBlocksU, TPB, POST_SMEM>>>(
        acc_i, h_i, nullptr, B16 + 2 * 8192, b2_ui, out_item, NI, postBlocksI,
        acc_u, h_u, nullptr, B16 + 3 * 8192, b2_iu, out_user, NU,
        0);
}

// round 17
// speedup vs baseline: 1.2400x; 1.1083x over previous
#include <cuda_runtime.h>
#include <cuda_bf16.h>
#include <cuda_fp16.h>
#include <cstdint>

#define NU 200000
#define NI 200000
#define D  64
#define MAXE 2000000
#define NB_I ((NI + 255) / 256)
#define NB_U ((NU + 255) / 256)

// ---------------------------------------------------------------------------
// Device scratch (no cudaMalloc allowed)
// ---------------------------------------------------------------------------
__device__ __half g_acc_i[(size_t)NI * D];   // fp16 aggregated means
__device__ __half g_acc_u[(size_t)NU * D];
__device__ float g_h_i[(size_t)NI * D];      // fp32 hidden (full-precision gather)
__device__ float g_h_u[(size_t)NU * D];
__device__ int g_deg_i[NI];
__device__ int g_deg_u[NU];
__device__ int g_rp_i[NI + 1];
__device__ int g_rp_u[NU + 1];
__device__ int g_cur_i[NI];
__device__ int g_cur_u[NU];
__device__ int g_perm_ui[MAXE];
__device__ int g_perm_iu[MAXE];
__device__ int g_bsum_i[1024];
__device__ int g_boff_i[1024];
__device__ int g_bsum_u[1024];
__device__ int g_boff_u[1024];
__device__ __half g_B16[4][64 * 128];        // prepacked W^T, fp16

__device__ __forceinline__ uint32_t smem_to_u32(const void* p) {
    uint32_t a;
    asm("{ .reg .u64 t; cvta.to.shared.u64 t, %1; cvt.u32.u64 %0, t; }"
        : "=r"(a) : "l"(p));
    return a;
}

// ---------------------------------------------------------------------------
// Weight prepack (fp16) + zero deg arrays (replaces memsets)
// ---------------------------------------------------------------------------
__global__ void prepack_w_k(const float* __restrict__ W1l_ui, const float* __restrict__ W1r_ui,
                            const float* __restrict__ W1l_iu, const float* __restrict__ W1r_iu,
                            const float* __restrict__ W2l_ui, const float* __restrict__ W2r_ui,
                            const float* __restrict__ W2l_iu, const float* __restrict__ W2r_iu)
{
    int gid = blockIdx.x * blockDim.x + threadIdx.x;
    int stride = gridDim.x * blockDim.x;

    for (int j = gid; j < NI; j += stride) g_deg_i[j] = 0;
    for (int j = gid; j < NU; j += stride) g_deg_u[j] = 0;

    if (gid < 4 * 64 * 128) {
        int set = gid >> 13;
        int n = (gid >> 7) & 63;
        int k = gid & 127;
        const float* Wl; const float* Wr;
        switch (set) {
            case 0: Wl = W1l_ui; Wr = W1r_ui; break;
            case 1: Wl = W1l_iu; Wr = W1r_iu; break;
            case 2: Wl = W2l_ui; Wr = W2r_ui; break;
            default: Wl = W2l_iu; Wr = W2r_iu; break;
        }
        float w = (k < 64) ? Wl[k * D + n] : Wr[(k - 64) * D + n];
        g_B16[set][n * 128 + k] = __float2half_rn(w);
    }
}

// ---------------------------------------------------------------------------
// CSR build — both sides per launch (R11 versions)
// ---------------------------------------------------------------------------
__global__ void hist2_k(const int* __restrict__ dst0, int E0, int* __restrict__ deg0,
                        const int* __restrict__ dst1, int E1, int* __restrict__ deg1)
{
    int i = blockIdx.x * blockDim.x + threadIdx.x;
    if (i < E0) atomicAdd(&deg0[__ldg(dst0 + i)], 1);
    else if (i < E0 + E1) atomicAdd(&deg1[__ldg(dst1 + (i - E0))], 1);
}

__global__ void scanA2_k(const int* __restrict__ deg0, int N0, int* __restrict__ bsum0,
                         const int* __restrict__ deg1, int N1, int* __restrict__ bsum1,
                         int nb0)
{
    __shared__ int s[256];
    int tid = threadIdx.x;
    int side = blockIdx.x >= nb0;
    int blk = side ? blockIdx.x - nb0 : blockIdx.x;
    const int* deg = side ? deg1 : deg0;
    int N = side ? N1 : N0;
    int* bsum = side ? bsum1 : bsum0;
    int i = blk * 256 + tid;
    s[tid] = (i < N) ? deg[i] : 0;
    __syncthreads();
    #pragma unroll
    for (int o = 128; o; o >>= 1) {
        if (tid < o) s[tid] += s[tid + o];
        __syncthreads();
    }
    if (tid == 0) bsum[blk] = s[0];
}

__global__ void scanB2_k(const int* __restrict__ bsum0, int NB0, int* __restrict__ boff0,
                         int* __restrict__ rp0, int N0,
                         const int* __restrict__ bsum1, int NB1, int* __restrict__ boff1,
                         int* __restrict__ rp1, int N1)
{
    __shared__ int s[1024];
    int tid = threadIdx.x;
    const int* bsum = blockIdx.x ? bsum1 : bsum0;
    int NB = blockIdx.x ? NB1 : NB0;
    int* boff = blockIdx.x ? boff1 : boff0;
    int* rowptr = blockIdx.x ? rp1 : rp0;
    int N = blockIdx.x ? N1 : N0;
    int v = (tid < NB) ? bsum[tid] : 0;
    s[tid] = v;
    __syncthreads();
    for (int o = 1; o < 1024; o <<= 1) {
        int t = (tid >= o) ? s[tid - o] : 0;
        __syncthreads();
        s[tid] += t;
        __syncthreads();
    }
    if (tid < NB) boff[tid] = s[tid] - v;
    if (tid == NB - 1) rowptr[N] = s[tid];
}

__global__ void scanC2_k(const int* __restrict__ deg0, int N0, const int* __restrict__ boff0,
                         int* __restrict__ rp0, int* __restrict__ cur0,
                         const int* __restrict__ deg1, int N1, const int* __restrict__ boff1,
                         int* __restrict__ rp1, int* __restrict__ cur1,
                         int nb0)
{
    __shared__ int s[256];
    int tid = threadIdx.x;
    int side = blockIdx.x >= nb0;
    int blk = side ? blockIdx.x - nb0 : blockIdx.x;
    const int* deg = side ? deg1 : deg0;
    const int* boff = side ? boff1 : boff0;
    int N = side ? N1 : N0;
    int* rowptr = side ? rp1 : rp0;
    int* cursor = side ? cur1 : cur0;
    int i = blk * 256 + tid;
    int v = (i < N) ? deg[i] : 0;
    s[tid] = v;
    __syncthreads();
    #pragma unroll
    for (int o = 1; o < 256; o <<= 1) {
        int t = (tid >= o) ? s[tid - o] : 0;
        __syncthreads();
        s[tid] += t;
        __syncthreads();
    }
    if (i < N) {
        int ex = boff[blk] + s[tid] - v;
        rowptr[i] = ex;
        cursor[i] = ex;
    }
}

__global__ void permute2_k(const int* __restrict__ e0, int E0,
                           int* __restrict__ cur0, int* __restrict__ perm0,
                           const int* __restrict__ e1, int E1,
                           int* __restrict__ cur1, int* __restrict__ perm1)
{
    int i = blockIdx.x * blockDim.x + threadIdx.x;
    if (i < E0) {
        int s = __ldg(e0 + i);
        int d = __ldg(e0 + E0 + i);
        perm0[atomicAdd(&cur0[d], 1)] = s;
    } else if (i < E0 + E1) {
        int j = i - E0;
        int s = __ldg(e1 + j);
        int d = __ldg(e1 + E1 + j);
        perm1[atomicAdd(&cur1[d], 1)] = s;
    }
}

// ---------------------------------------------------------------------------
// Gather-side aggregation (mean). fp32 gathers, fp32 accumulate, fp16 store
// (same rounding point the post would apply — zero extra error).
// ---------------------------------------------------------------------------
__global__ void __launch_bounds__(256)
agg2_k(const float* __restrict__ src0, const int* __restrict__ remap0,
       const int* __restrict__ rp0, const int* __restrict__ perm0,
       __half* __restrict__ out0, int N0,
       const float* __restrict__ src1, const int* __restrict__ remap1,
       const int* __restrict__ rp1, const int* __restrict__ perm1,
       __half* __restrict__ out1, int N1)
{
    int w = (blockIdx.x * blockDim.x + threadIdx.x) >> 5;
    int lane = threadIdx.x & 31;
    if (w >= N0 + N1) return;

    const float* src; const int* remap; const int* rowptr; const int* perm;
    __half* outm;
    if (w < N0) {
        src = src0; remap = remap0; rowptr = rp0; perm = perm0; outm = out0;
    } else {
        w -= N0;
        src = src1; remap = remap1; rowptr = rp1; perm = perm1; outm = out1;
    }

    int start = __ldg(rowptr + w);
    int end   = __ldg(rowptr + w + 1);

    float ax = 0.0f, ay = 0.0f;
    for (int base = start; base < end; base += 32) {
        int rem = end - base;
        int idx = 0;
        if (lane < rem) {
            idx = __ldg(perm + base + lane);
            if (remap) idx = __ldg(remap + idx);
        }
        int m = rem < 32 ? rem : 32;
        for (int j = 0; j < m; j++) {
            int s2 = __shfl_sync(0xffffffffu, idx, j);
            float2 v = *reinterpret_cast<const float2*>(src + (size_t)s2 * D + lane * 2);
            ax += v.x;
            ay += v.y;
        }
    }

    int deg = end - start;
    float inv = (deg > 0) ? (1.0f / (float)deg) : 0.0f;
    __half2 o = __floats2half2_rn(ax * inv, ay * inv);
    *reinterpret_cast<__half2*>(outm + (size_t)w * D + lane * 2) = o;
}

// ---------------------------------------------------------------------------
// Post GEMM — single-pass fp16 MMA (R16 kernel), acc now fp16 (direct copy).
// ---------------------------------------------------------------------------
#define PKB 272
#define SM_A    0
#define SM_B    (128 * PKB)
#define SM_BIAS (SM_B + 64 * PKB)
#define POST_SMEM (SM_BIAS + 256)

#define LDMATRIX_X4(r0, r1, r2, r3, addr) \
    asm volatile("ldmatrix.sync.aligned.m8n8.x4.shared.b16 {%0, %1, %2, %3}, [%4];" \
                 : "=r"(r0), "=r"(r1), "=r"(r2), "=r"(r3) : "r"(addr))

#define MMA_F16(d, a0, a1, a2, a3, b0, b1) \
    asm volatile("mma.sync.aligned.m16n8k16.row.col.f32.f16.f16.f32 " \
                 "{%0, %1, %2, %3}, {%4, %5, %6, %7}, {%8, %9}, {%0, %1, %2, %3};" \
                 : "+f"((d)[0]), "+f"((d)[1]), "+f"((d)[2]), "+f"((d)[3]) \
                 : "r"(a0), "r"(a1), "r"(a2), "r"(a3), "r"(b0), "r"(b1))

__device__ __forceinline__ uint32_t h2u(__half2 v) {
    return *reinterpret_cast<uint32_t*>(&v);
}

__global__ void __launch_bounds__(256)
sage_post2_tc(const __half* __restrict__ acc0, const float* __restrict__ x0,
              const int* __restrict__ remap0,
              const __half* __restrict__ B0,
              const float* __restrict__ bl0, float* __restrict__ out0, int N0, int nb0,
              const __half* __restrict__ acc1, const float* __restrict__ x1,
              const int* __restrict__ remap1,
              const __half* __restrict__ B1,
              const float* __restrict__ bl1, float* __restrict__ out1, int N1,
              int relu)
{
    extern __shared__ char smem[];
    uint32_t sb = smem_to_u32(smem);
    const int tid = threadIdx.x;
    const int warp = tid >> 5;
    const int lane = tid & 31;

    const int side = blockIdx.x >= nb0;
    const __half* acc = side ? acc1 : acc0;
    const float* xdst_base = side ? x1 : x0;
    const int* remap = side ? remap1 : remap0;
    const __half* B = side ? B1 : B0;
    const float* bl = side ? bl1 : bl0;
    float* out = side ? out1 : out0;
    const int N = side ? N1 : N0;
    const int r0 = (side ? blockIdx.x - nb0 : blockIdx.x) * 128;

    // ---- Stage B (fp16, vectorized) ----
    #pragma unroll
    for (int pp = 0; pp < 4; pp++) {
        int i = tid + pp * 256;
        int n = i >> 4;
        int kq = i & 15;
        *reinterpret_cast<uint4*>(smem + SM_B + n * PKB + kq * 16) =
            *reinterpret_cast<const uint4*>(B + n * 128 + kq * 8);
    }
    if (tid < 64) *reinterpret_cast<float*>(smem + SM_BIAS + tid * 4) = bl[tid];

    // ---- Stage A: half 0 = fp16 acc (direct copy), half 1 = fp32 x (cvt) ----
    {
        int row  = tid & 127;
        int half = tid >> 7;
        int gr   = r0 + row;
        bool ok  = (gr < N);
        char* aRow = smem + SM_A + row * PKB + half * 128;
        if (half == 0) {
            const __half* p16 = acc + (size_t)(ok ? gr : 0) * D;
            #pragma unroll
            for (int j = 0; j < 8; j++) {
                uint4 v = ok ? reinterpret_cast<const uint4*>(p16)[j]
                             : make_uint4(0u, 0u, 0u, 0u);
                *reinterpret_cast<uint4*>(aRow + j * 16) = v;
            }
        } else {
            int xr = ok ? (remap ? __ldg(remap + gr) : gr) : 0;
            const float* p = xdst_base + (size_t)xr * D;
            #pragma unroll
            for (int j = 0; j < 8; j++) {
                float4 v0 = ok ? reinterpret_cast<const float4*>(p)[j * 2]
                               : make_float4(0.f, 0.f, 0.f, 0.f);
                float4 v1 = ok ? reinterpret_cast<const float4*>(p)[j * 2 + 1]
                               : make_float4(0.f, 0.f, 0.f, 0.f);
                __half2 h0 = __floats2half2_rn(v0.x, v0.y);
                __half2 h1 = __floats2half2_rn(v0.z, v0.w);
                __half2 h2 = __floats2half2_rn(v1.x, v1.y);
                __half2 h3 = __floats2half2_rn(v1.z, v1.w);
                *reinterpret_cast<uint4*>(aRow + j * 16) =
                    make_uint4(h2u(h0), h2u(h1), h2u(h2), h2u(h3));
            }
        }
    }
    __syncthreads();

    // ---- MMA mainloop: single pass, 8 k-steps, 8 n-tiles ----
    float d[8][4];
    #pragma unroll
    for (int t = 0; t < 8; t++) {
        d[t][0] = 0.f; d[t][1] = 0.f; d[t][2] = 0.f; d[t][3] = 0.f;
    }

    const uint32_t aRowOff = (uint32_t)(warp * 16 + (lane & 15)) * PKB
                           + (uint32_t)(lane >> 4) * 16;
    const uint32_t bRowOff = (uint32_t)(lane >> 2) * PKB + (uint32_t)(lane & 3) * 4;

    const uint32_t aBase = sb + SM_A + aRowOff;
    #pragma unroll
    for (int ks = 0; ks < 8; ks++) {
        uint32_t a0, a1, a2, a3;
        LDMATRIX_X4(a0, a1, a2, a3, aBase + ks * 32);
        #pragma unroll
        for (int t = 0; t < 8; t++) {
            uint32_t b0 = *reinterpret_cast<const uint32_t*>(
                (const char*)smem + SM_B + bRowOff + t * 8 * PKB + ks * 32);
            uint32_t b1 = *reinterpret_cast<const uint32_t*>(
                (const char*)smem + SM_B + bRowOff + t * 8 * PKB + ks * 32 + 16);
            MMA_F16(d[t], a0, a1, a2, a3, b0, b1);
        }
    }

    // ---- Epilogue ----
    const float* bias = reinterpret_cast<const float*>(smem + SM_BIAS);
    int cBase = (lane & 3) * 2;
    float ssl = 0.f, ssh = 0.f;
    #pragma unroll
    for (int t = 0; t < 8; t++) {
        int c = t * 8 + cBase;
        float b0 = bias[c], b1 = bias[c + 1];
        d[t][0] += b0; d[t][1] += b1;
        d[t][2] += b0; d[t][3] += b1;
        ssl = fmaf(d[t][0], d[t][0], ssl); ssl = fmaf(d[t][1], d[t][1], ssl);
        ssh = fmaf(d[t][2], d[t][2], ssh); ssh = fmaf(d[t][3], d[t][3], ssh);
    }
    ssl += __shfl_xor_sync(0xffffffffu, ssl, 1);
    ssl += __shfl_xor_sync(0xffffffffu, ssl, 2);
    ssh += __shfl_xor_sync(0xffffffffu, ssh, 1);
    ssh += __shfl_xor_sync(0xffffffffu, ssh, 2);

    int rlo = r0 + warp * 16 + (lane >> 2);
    int rhi = rlo + 8;
    float invl = 1.0f / fmaxf(sqrtf(ssl), 1e-12f);
    float invh = 1.0f / fmaxf(sqrtf(ssh), 1e-12f);

    if (rlo < N) {
        float* op = out + (size_t)rlo * D + cBase;
        #pragma unroll
        for (int t = 0; t < 8; t++) {
            float2 v = make_float2(d[t][0] * invl, d[t][1] * invl);
            if (relu) { v.x = fmaxf(v.x, 0.f); v.y = fmaxf(v.y, 0.f); }
            *reinterpret_cast<float2*>(op + t * 8) = v;
        }
    }
    if (rhi < N) {
        float* op = out + (size_t)rhi * D + cBase;
        #pragma unroll
        for (int t = 0; t < 8; t++) {
            float2 v = make_float2(d[t][2] * invh, d[t][3] * invh);
            if (relu) { v.x = fmaxf(v.x, 0.f); v.y = fmaxf(v.y, 0.f); }
            *reinterpret_cast<float2*>(op + t * 8) = v;
        }
    }
}

// ---------------------------------------------------------------------------
// Launch
// ---------------------------------------------------------------------------
extern "C" void kernel_launch(void* const* d_in, const int* in_sizes, int n_in,
                              void* d_out, int out_size)
{
    const float* emb_user = (const float*)d_in[0];
    const float* emb_item = (const float*)d_in[1];
    const float* W1l_ui = (const float*)d_in[2];
    const float* b1_ui  = (const float*)d_in[3];
    const float* W1r_ui = (const float*)d_in[4];
    const float* W1l_iu = (const float*)d_in[5];
    const float* b1_iu  = (const float*)d_in[6];
    const float* W1r_iu = (const float*)d_in[7];
    const float* W2l_ui = (const float*)d_in[8];
    const float* b2_ui  = (const float*)d_in[9];
    const float* W2r_ui = (const float*)d_in[10];
    const float* W2l_iu = (const float*)d_in[11];
    const float* b2_iu  = (const float*)d_in[12];
    const float* W2r_iu = (const float*)d_in[13];
    const int* n_id_user = (const int*)d_in[14];
    const int* n_id_item = (const int*)d_in[15];
    const int* edge_ui   = (const int*)d_in[16];
    const int* edge_iu   = (const int*)d_in[17];

    const int E_ui = in_sizes[16] / 2;
    const int E_iu = in_sizes[17] / 2;

    float* out = (float*)d_out;
    float* out_user = out;
    float* out_item = out + (size_t)NU * D;

    __half *acc_i, *acc_u;
    float *h_i, *h_u;
    int *deg_i, *deg_u, *rp_i, *rp_u, *cur_i, *cur_u, *perm_ui, *perm_iu;
    int *bsum_i, *boff_i, *bsum_u, *boff_u;
    __half* B16;
    cudaGetSymbolAddress((void**)&acc_i, g_acc_i);
    cudaGetSymbolAddress((void**)&acc_u, g_acc_u);
    cudaGetSymbolAddress((void**)&h_i, g_h_i);
    cudaGetSymbolAddress((void**)&h_u, g_h_u);
    cudaGetSymbolAddress((void**)&deg_i, g_deg_i);
    cudaGetSymbolAddress((void**)&deg_u, g_deg_u);
    cudaGetSymbolAddress((void**)&rp_i, g_rp_i);
    cudaGetSymbolAddress((void**)&rp_u, g_rp_u);
    cudaGetSymbolAddress((void**)&cur_i, g_cur_i);
    cudaGetSymbolAddress((void**)&cur_u, g_cur_u);
    cudaGetSymbolAddress((void**)&perm_ui, g_perm_ui);
    cudaGetSymbolAddress((void**)&perm_iu, g_perm_iu);
    cudaGetSymbolAddress((void**)&bsum_i, g_bsum_i);
    cudaGetSymbolAddress((void**)&boff_i, g_boff_i);
    cudaGetSymbolAddress((void**)&bsum_u, g_bsum_u);
    cudaGetSymbolAddress((void**)&boff_u, g_boff_u);
    cudaGetSymbolAddress((void**)&B16, g_B16);

    const int TPB = 256;
    const int eBlocks2 = (E_ui + E_iu + TPB - 1) / TPB;
    const int aggBlocks2 = (int)(((long long)(NI + NU) * 32 + TPB - 1) / TPB);
    const int postBlocksI = (NI + 127) / 128;
    const int postBlocksU = (NU + 127) / 128;

    cudaFuncSetAttribute(sage_post2_tc,
                         cudaFuncAttributeMaxDynamicSharedMemorySize, POST_SMEM);

    // ---- Prepack (fp16 weights) + zero deg ----
    prepack_w_k<<<800, 256>>>(W1l_ui, W1r_ui, W1l_iu, W1r_iu,
                              W2l_ui, W2r_ui, W2l_iu, W2r_iu);

    // ---- CSR build ----
    hist2_k<<<eBlocks2, TPB>>>(edge_ui + E_ui, E_ui, deg_i,
                               edge_iu + E_iu, E_iu, deg_u);
    scanA2_k<<<NB_I + NB_U, 256>>>(deg_i, NI, bsum_i, deg_u, NU, bsum_u, NB_I);
    scanB2_k<<<2, 1024>>>(bsum_i, NB_I, boff_i, rp_i, NI,
                          bsum_u, NB_U, boff_u, rp_u, NU);
    scanC2_k<<<NB_I + NB_U, 256>>>(deg_i, NI, boff_i, rp_i, cur_i,
                                   deg_u, NU, boff_u, rp_u, cur_u, NB_I);
    permute2_k<<<eBlocks2, TPB>>>(edge_ui, E_ui, cur_i, perm_ui,
                                  edge_iu, E_iu, cur_u, perm_iu);

    // ---- Layer 1 ----
    agg2_k<<<aggBlocks2, TPB>>>(emb_user, n_id_user, rp_i, perm_ui, acc_i, NI,
                                emb_item, n_id_item, rp_u, perm_iu, acc_u, NU);
    sage_post2_tc<<<postBlocksI + postBlocksU, TPB, POST_SMEM>>>(
        acc_i, emb_item, n_id_item, B16 + 0 * 8192, b1_ui, h_i, NI, postBlocksI,
        acc_u, emb_user, n_id_user, B16 + 1 * 8192, b1_iu, h_u, NU,
        1);

    // ---- Layer 2 ----
    agg2_k<<<aggBlocks2, TPB>>>(h_u, nullptr, rp_i, perm_ui, acc_i, NI,
                                h_i, nullptr, rp_u, perm_iu, acc_u, NU);
    sage_post2_tc<<<postBlocksI + postBlocksU, TPB, POST_SMEM>>>(
        acc_i, h_i, nullptr, B16 + 2 * 8192, b2_ui, out_item, NI, postBlocksI,
        acc_u, h_u, nullptr, B16 + 3 * 8192, b2_iu, out_user, NU,
        0);
}